// round 1
// baseline (speedup 1.0000x reference)
#include <cuda_runtime.h>

// NativeSparseAttention: S=8192, B=16, E=128, fp32
// one CTA per sequence position s; 256 threads.
// thread t: e = t>>1 (score row), h = t&1 (column half / b half)

#define S_TOTAL 8192
#define B_DIM 16
#define E_DIM 128

__global__ __launch_bounds__(256, 2)
void nsa_kernel(const float* __restrict__ x,
                const float* __restrict__ Wk,
                const float* __restrict__ bk,
                const float* __restrict__ Wv,
                const float* __restrict__ bv,
                float* __restrict__ out) {
    __shared__ float xs[B_DIM][E_DIM];
    __shared__ float ks[B_DIM][E_DIM];
    __shared__ float vs[B_DIM][E_DIM];

    const int s = blockIdx.x;
    const int t = threadIdx.x;

    // ---- load x[s] (2048 floats) coalesced ----
    {
        const float4* xg = reinterpret_cast<const float4*>(x + (size_t)s * B_DIM * E_DIM);
        float4* xs4 = reinterpret_cast<float4*>(&xs[0][0]);
        xs4[t]       = xg[t];
        xs4[t + 256] = xg[t + 256];
    }
    __syncthreads();

    const int e = t >> 1;   // 0..127
    const int h = t & 1;    // 0 or 1

    // ---- phase 1: k = x@Wk^T + bk, v = x@Wv^T + bv ----
    // thread computes k[b][e], v[b][e] for b in [h*8, h*8+8)
    {
        const float4* wk4 = reinterpret_cast<const float4*>(Wk + (size_t)e * E_DIM);
        const float4* wv4 = reinterpret_cast<const float4*>(Wv + (size_t)e * E_DIM);
        const float bke = bk[e];
        const float bve = bv[e];
        float acck[8], accv[8];
        #pragma unroll
        for (int bb = 0; bb < 8; bb++) { acck[bb] = bke; accv[bb] = bve; }

        #pragma unroll 8
        for (int j = 0; j < 32; j++) {
            const float4 wk = wk4[j];
            const float4 wv = wv4[j];
            #pragma unroll
            for (int bb = 0; bb < 8; bb++) {
                const float4 xv = *reinterpret_cast<const float4*>(&xs[h * 8 + bb][j * 4]);
                acck[bb] = fmaf(xv.x, wk.x, fmaf(xv.y, wk.y, fmaf(xv.z, wk.z, fmaf(xv.w, wk.w, acck[bb]))));
                accv[bb] = fmaf(xv.x, wv.x, fmaf(xv.y, wv.y, fmaf(xv.z, wv.z, fmaf(xv.w, wv.w, accv[bb]))));
            }
        }
        #pragma unroll
        for (int bb = 0; bb < 8; bb++) {
            ks[h * 8 + bb][e] = acck[bb];
            vs[h * 8 + bb][e] = accv[bb];
        }
    }
    __syncthreads();

    // ---- phase 2: scores[e][f] = sum_b k[b][e] * v[b][f], f in [h*64, h*64+64) ----
    float sc[64];
    #pragma unroll
    for (int i = 0; i < 64; i++) sc[i] = 0.0f;

    #pragma unroll 4
    for (int b = 0; b < B_DIM; b++) {
        const float kv = ks[b][e];
        const float4* vrow = reinterpret_cast<const float4*>(&vs[b][h * 64]);
        #pragma unroll
        for (int i = 0; i < 16; i++) {
            const float4 v4 = vrow[i];
            sc[4 * i + 0] = fmaf(kv, v4.x, sc[4 * i + 0]);
            sc[4 * i + 1] = fmaf(kv, v4.y, sc[4 * i + 1]);
            sc[4 * i + 2] = fmaf(kv, v4.z, sc[4 * i + 2]);
            sc[4 * i + 3] = fmaf(kv, v4.w, sc[4 * i + 3]);
        }
    }

    // ---- softmax over f (row e spans thread pair (2e, 2e+1)) ----
    // probs = softmax(scores * 1/sqrt(8192)); keep exp unnormalized, divide at end
    const float scale = 0.01104854345603993f; // 1/sqrt(8192)
    float m = -1e30f;
    #pragma unroll
    for (int i = 0; i < 64; i++) m = fmaxf(m, sc[i]);
    m = fmaxf(m, __shfl_xor_sync(0xffffffffu, m, 1));

    float ssum = 0.0f;
    #pragma unroll
    for (int i = 0; i < 64; i++) {
        sc[i] = __expf((sc[i] - m) * scale);
        ssum += sc[i];
    }
    ssum += __shfl_xor_sync(0xffffffffu, ssum, 1);
    const float inv = 1.0f / ssum;

    // ---- phase 3: out[b][e] = inv * sum_f exp[e][f] * x[b][f] ----
    float o[B_DIM];
    #pragma unroll
    for (int b = 0; b < B_DIM; b++) o[b] = 0.0f;

    #pragma unroll 4
    for (int i = 0; i < 16; i++) {
        const float p0 = sc[4 * i + 0];
        const float p1 = sc[4 * i + 1];
        const float p2 = sc[4 * i + 2];
        const float p3 = sc[4 * i + 3];
        #pragma unroll
        for (int b = 0; b < B_DIM; b++) {
            const float4 xv = *reinterpret_cast<const float4*>(&xs[b][h * 64 + i * 4]);
            o[b] = fmaf(p0, xv.x, fmaf(p1, xv.y, fmaf(p2, xv.z, fmaf(p3, xv.w, o[b]))));
        }
    }

    float* outp = out + (size_t)s * B_DIM * E_DIM;
    #pragma unroll
    for (int b = 0; b < B_DIM; b++) {
        const float tot = o[b] + __shfl_xor_sync(0xffffffffu, o[b], 1);
        if (h == 0) outp[b * E_DIM + e] = tot * inv;
    }
}

extern "C" void kernel_launch(void* const* d_in, const int* in_sizes, int n_in,
                              void* d_out, int out_size) {
    const float* x  = (const float*)d_in[0];
    const float* Wk = (const float*)d_in[1];
    const float* bk = (const float*)d_in[2];
    const float* Wv = (const float*)d_in[3];
    const float* bv = (const float*)d_in[4];
    float* out = (float*)d_out;
    nsa_kernel<<<S_TOTAL, 256>>>(x, Wk, bk, Wv, bv, out);
}

// round 2
// speedup vs baseline: 1.0003x; 1.0003x over previous
#include <cuda_runtime.h>

// NativeSparseAttention: S=8192, B=16, E=128, fp32
// one CTA per sequence position s; 256 threads.
// thread t: e = t>>1 (score row), h = t&1 (column half / b half)

#define S_TOTAL 8192
#define B_DIM 16
#define E_DIM 128

__global__ __launch_bounds__(256, 2)
void nsa_kernel(const float* __restrict__ x,
                const float* __restrict__ Wk,
                const float* __restrict__ bk,
                const float* __restrict__ Wv,
                const float* __restrict__ bv,
                float* __restrict__ out) {
    __shared__ float xs[B_DIM][E_DIM];
    __shared__ float ks[B_DIM][E_DIM];
    __shared__ float vs[B_DIM][E_DIM];

    const int s = blockIdx.x;
    const int t = threadIdx.x;

    // ---- load x[s] (2048 floats) coalesced ----
    {
        const float4* xg = reinterpret_cast<const float4*>(x + (size_t)s * B_DIM * E_DIM);
        float4* xs4 = reinterpret_cast<float4*>(&xs[0][0]);
        xs4[t]       = xg[t];
        xs4[t + 256] = xg[t + 256];
    }
    __syncthreads();

    const int e = t >> 1;   // 0..127
    const int h = t & 1;    // 0 or 1

    // ---- phase 1: k = x@Wk^T + bk, v = x@Wv^T + bv ----
    // thread computes k[b][e], v[b][e] for b in [h*8, h*8+8)
    {
        const float4* wk4 = reinterpret_cast<const float4*>(Wk + (size_t)e * E_DIM);
        const float4* wv4 = reinterpret_cast<const float4*>(Wv + (size_t)e * E_DIM);
        const float bke = bk[e];
        const float bve = bv[e];
        float acck[8], accv[8];
        #pragma unroll
        for (int bb = 0; bb < 8; bb++) { acck[bb] = bke; accv[bb] = bve; }

        #pragma unroll 8
        for (int j = 0; j < 32; j++) {
            const float4 wk = wk4[j];
            const float4 wv = wv4[j];
            #pragma unroll
            for (int bb = 0; bb < 8; bb++) {
                const float4 xv = *reinterpret_cast<const float4*>(&xs[h * 8 + bb][j * 4]);
                acck[bb] = fmaf(xv.x, wk.x, fmaf(xv.y, wk.y, fmaf(xv.z, wk.z, fmaf(xv.w, wk.w, acck[bb]))));
                accv[bb] = fmaf(xv.x, wv.x, fmaf(xv.y, wv.y, fmaf(xv.z, wv.z, fmaf(xv.w, wv.w, accv[bb]))));
            }
        }
        #pragma unroll
        for (int bb = 0; bb < 8; bb++) {
            ks[h * 8 + bb][e] = acck[bb];
            vs[h * 8 + bb][e] = accv[bb];
        }
    }
    __syncthreads();

    // ---- phase 2: scores[e][f] = sum_b k[b][e] * v[b][f], f in [h*64, h*64+64) ----
    float sc[64];
    #pragma unroll
    for (int i = 0; i < 64; i++) sc[i] = 0.0f;

    #pragma unroll 4
    for (int b = 0; b < B_DIM; b++) {
        const float kv = ks[b][e];
        const float4* vrow = reinterpret_cast<const float4*>(&vs[b][h * 64]);
        #pragma unroll
        for (int i = 0; i < 16; i++) {
            const float4 v4 = vrow[i];
            sc[4 * i + 0] = fmaf(kv, v4.x, sc[4 * i + 0]);
            sc[4 * i + 1] = fmaf(kv, v4.y, sc[4 * i + 1]);
            sc[4 * i + 2] = fmaf(kv, v4.z, sc[4 * i + 2]);
            sc[4 * i + 3] = fmaf(kv, v4.w, sc[4 * i + 3]);
        }
    }

    // ---- softmax over f (row e spans thread pair (2e, 2e+1)) ----
    // probs = softmax(scores * 1/sqrt(8192)); keep exp unnormalized, divide at end
    const float scale = 0.01104854345603993f; // 1/sqrt(8192)
    float m = -1e30f;
    #pragma unroll
    for (int i = 0; i < 64; i++) m = fmaxf(m, sc[i]);
    m = fmaxf(m, __shfl_xor_sync(0xffffffffu, m, 1));

    float ssum = 0.0f;
    #pragma unroll
    for (int i = 0; i < 64; i++) {
        sc[i] = __expf((sc[i] - m) * scale);
        ssum += sc[i];
    }
    ssum += __shfl_xor_sync(0xffffffffu, ssum, 1);
    const float inv = 1.0f / ssum;

    // ---- phase 3: out[b][e] = inv * sum_f exp[e][f] * x[b][f] ----
    float o[B_DIM];
    #pragma unroll
    for (int b = 0; b < B_DIM; b++) o[b] = 0.0f;

    #pragma unroll 4
    for (int i = 0; i < 16; i++) {
        const float p0 = sc[4 * i + 0];
        const float p1 = sc[4 * i + 1];
        const float p2 = sc[4 * i + 2];
        const float p3 = sc[4 * i + 3];
        #pragma unroll
        for (int b = 0; b < B_DIM; b++) {
            const float4 xv = *reinterpret_cast<const float4*>(&xs[b][h * 64 + i * 4]);
            o[b] = fmaf(p0, xv.x, fmaf(p1, xv.y, fmaf(p2, xv.z, fmaf(p3, xv.w, o[b]))));
        }
    }

    float* outp = out + (size_t)s * B_DIM * E_DIM;
    #pragma unroll
    for (int b = 0; b < B_DIM; b++) {
        const float tot = o[b] + __shfl_xor_sync(0xffffffffu, o[b], 1);
        if (h == 0) outp[b * E_DIM + e] = tot * inv;
    }
}

extern "C" void kernel_launch(void* const* d_in, const int* in_sizes, int n_in,
                              void* d_out, int out_size) {
    const float* x  = (const float*)d_in[0];
    const float* Wk = (const float*)d_in[1];
    const float* bk = (const float*)d_in[2];
    const float* Wv = (const float*)d_in[3];
    const float* bv = (const float*)d_in[4];
    float* out = (float*)d_out;
    nsa_kernel<<<S_TOTAL, 256>>>(x, Wk, bk, Wv, bv, out);
}

// round 3
// speedup vs baseline: 1.0970x; 1.0966x over previous
#include <cuda_runtime.h>

// NativeSparseAttention: S=8192, B=16, E=128, fp32
// one CTA per sequence position s; 256 threads.

#define S_TOTAL 8192
#define B_DIM 16
#define E_DIM 128

__global__ __launch_bounds__(256, 2)
void nsa_kernel(const float* __restrict__ x,
                const float* __restrict__ Wk,
                const float* __restrict__ bk,
                const float* __restrict__ Wv,
                const float* __restrict__ bv,
                float* __restrict__ out) {
    __shared__ float xs[B_DIM][E_DIM];
    __shared__ float ks[B_DIM][E_DIM];
    __shared__ float vs[B_DIM][E_DIM];

    const int s = blockIdx.x;
    const int t = threadIdx.x;

    // ---- load x[s] (2048 floats) coalesced ----
    {
        const float4* xg = reinterpret_cast<const float4*>(x + (size_t)s * B_DIM * E_DIM);
        float4* xs4 = reinterpret_cast<float4*>(&xs[0][0]);
        xs4[t]       = xg[t];
        xs4[t + 256] = xg[t + 256];
    }
    __syncthreads();

    // ---- phase 1: k = x@Wk^T + bk, v = x@Wv^T + bv (unchanged, known-good) ----
    {
        const int e1 = t >> 1;   // 0..127
        const int h1 = t & 1;    // 0 or 1
        const float4* wk4 = reinterpret_cast<const float4*>(Wk + (size_t)e1 * E_DIM);
        const float4* wv4 = reinterpret_cast<const float4*>(Wv + (size_t)e1 * E_DIM);
        const float bke = bk[e1];
        const float bve = bv[e1];
        float acck[8], accv[8];
        #pragma unroll
        for (int bb = 0; bb < 8; bb++) { acck[bb] = bke; accv[bb] = bve; }

        #pragma unroll 8
        for (int j = 0; j < 32; j++) {
            const float4 wk = wk4[j];
            const float4 wv = wv4[j];
            #pragma unroll
            for (int bb = 0; bb < 8; bb++) {
                const float4 xv = *reinterpret_cast<const float4*>(&xs[h1 * 8 + bb][j * 4]);
                acck[bb] = fmaf(xv.x, wk.x, fmaf(xv.y, wk.y, fmaf(xv.z, wk.z, fmaf(xv.w, wk.w, acck[bb]))));
                accv[bb] = fmaf(xv.x, wv.x, fmaf(xv.y, wv.y, fmaf(xv.z, wv.z, fmaf(xv.w, wv.w, accv[bb]))));
            }
        }
        #pragma unroll
        for (int bb = 0; bb < 8; bb++) {
            ks[h1 * 8 + bb][e1] = acck[bb];
            vs[h1 * 8 + bb][e1] = accv[bb];
        }
    }
    __syncthreads();

    // ---- new thread mapping for phases 2/3 ----
    // thread t owns score tile rows e0..e0+3, cols f0..f0+15
    const int fgrp = t & 7;          // 8 column groups of 16
    const int f0   = fgrp * 16;
    const int e0   = (t >> 3) * 4;   // 32 row groups of 4

    // ---- phase 2: sc[r][c] = sum_b k[b][e0+r] * v[b][f0+c] ----
    float sc[4][16];
    #pragma unroll
    for (int r = 0; r < 4; r++)
        #pragma unroll
        for (int c = 0; c < 16; c++) sc[r][c] = 0.0f;

    #pragma unroll 2
    for (int b = 0; b < B_DIM; b++) {
        const float4 kk = *reinterpret_cast<const float4*>(&ks[b][e0]);
        const float4* vrow = reinterpret_cast<const float4*>(&vs[b][f0]);
        const float4 v0 = vrow[0], v1 = vrow[1], v2 = vrow[2], v3 = vrow[3];
        const float vvals[16] = { v0.x, v0.y, v0.z, v0.w,
                                  v1.x, v1.y, v1.z, v1.w,
                                  v2.x, v2.y, v2.z, v2.w,
                                  v3.x, v3.y, v3.z, v3.w };
        const float kvals[4] = { kk.x, kk.y, kk.z, kk.w };
        #pragma unroll
        for (int r = 0; r < 4; r++)
            #pragma unroll
            for (int c = 0; c < 16; c++)
                sc[r][c] = fmaf(kvals[r], vvals[c], sc[r][c]);
    }

    // ---- softmax over f (each row spans 8 consecutive lanes) ----
    const float scale = 0.01104854345603993f; // 1/sqrt(8192)
    float inv[4];
    #pragma unroll
    for (int r = 0; r < 4; r++) {
        float m = sc[r][0];
        #pragma unroll
        for (int c = 1; c < 16; c++) m = fmaxf(m, sc[r][c]);
        m = fmaxf(m, __shfl_xor_sync(0xffffffffu, m, 1));
        m = fmaxf(m, __shfl_xor_sync(0xffffffffu, m, 2));
        m = fmaxf(m, __shfl_xor_sync(0xffffffffu, m, 4));

        float ssum = 0.0f;
        #pragma unroll
        for (int c = 0; c < 16; c++) {
            sc[r][c] = __expf((sc[r][c] - m) * scale);
            ssum += sc[r][c];
        }
        ssum += __shfl_xor_sync(0xffffffffu, ssum, 1);
        ssum += __shfl_xor_sync(0xffffffffu, ssum, 2);
        ssum += __shfl_xor_sync(0xffffffffu, ssum, 4);
        inv[r] = 1.0f / ssum;
    }

    // ---- phase 3: out[b][e0+r] = inv[r] * sum_f p[r][f] * x[b][f] ----
    // process b in 2 chunks of 8 to bound register pressure
    float* outp = out + (size_t)s * B_DIM * E_DIM;
    #pragma unroll
    for (int bc = 0; bc < 2; bc++) {
        float o[8][4];
        #pragma unroll
        for (int bb = 0; bb < 8; bb++)
            #pragma unroll
            for (int r = 0; r < 4; r++) o[bb][r] = 0.0f;

        #pragma unroll
        for (int bb = 0; bb < 8; bb++) {
            const int b = bc * 8 + bb;
            const float4* xrow = reinterpret_cast<const float4*>(&xs[b][f0]);
            const float4 x0 = xrow[0], x1 = xrow[1], x2 = xrow[2], x3 = xrow[3];
            const float xv[16] = { x0.x, x0.y, x0.z, x0.w,
                                   x1.x, x1.y, x1.z, x1.w,
                                   x2.x, x2.y, x2.z, x2.w,
                                   x3.x, x3.y, x3.z, x3.w };
            #pragma unroll
            for (int r = 0; r < 4; r++)
                #pragma unroll
                for (int c = 0; c < 16; c++)
                    o[bb][r] = fmaf(sc[r][c], xv[c], o[bb][r]);
        }

        // butterfly reduce over the 8 lanes sharing these rows
        #pragma unroll
        for (int bb = 0; bb < 8; bb++)
            #pragma unroll
            for (int r = 0; r < 4; r++) {
                o[bb][r] += __shfl_xor_sync(0xffffffffu, o[bb][r], 1);
                o[bb][r] += __shfl_xor_sync(0xffffffffu, o[bb][r], 2);
                o[bb][r] += __shfl_xor_sync(0xffffffffu, o[bb][r], 4);
            }

        // lane fgrp writes out[b = bc*8+fgrp][e0..e0+3] as one float4
        {
            const int b = bc * 8 + fgrp;
            float4 res;
            res.x = o[fgrp][0] * inv[0];
            res.y = o[fgrp][1] * inv[1];
            res.z = o[fgrp][2] * inv[2];
            res.w = o[fgrp][3] * inv[3];
            *reinterpret_cast<float4*>(&outp[b * E_DIM + e0]) = res;
        }
    }
}

extern "C" void kernel_launch(void* const* d_in, const int* in_sizes, int n_in,
                              void* d_out, int out_size) {
    const float* x  = (const float*)d_in[0];
    const float* Wk = (const float*)d_in[1];
    const float* bk = (const float*)d_in[2];
    const float* Wv = (const float*)d_in[3];
    const float* bv = (const float*)d_in[4];
    float* out = (float*)d_out;
    nsa_kernel<<<S_TOTAL, 256>>>(x, Wk, bk, Wv, bv, out);
}

// round 4
// speedup vs baseline: 2.4563x; 2.2392x over previous
#include <cuda_runtime.h>

// NativeSparseAttention: S=8192, B=16, E=128, fp32
// one CTA per sequence position s; 256 threads.
// thread t: eg = t>>3 (e-rows 4eg..4eg+3), jo = t&7 (j/f chunks {32i+4jo..+3})

#define S_TOTAL 8192
#define B_DIM 16
#define E_DIM 128

__global__ __launch_bounds__(256, 2)
void nsa_kernel(const float* __restrict__ x,
                const float* __restrict__ Wk,
                const float* __restrict__ bk,
                const float* __restrict__ Wv,
                const float* __restrict__ bv,
                float* __restrict__ out) {
    __shared__ float xs[B_DIM * E_DIM];
    __shared__ float ks[B_DIM * E_DIM];
    __shared__ float vs[B_DIM * E_DIM];

    const int s = blockIdx.x;
    const int t = threadIdx.x;
    const int eg = t >> 3;   // 0..31
    const int jo = t & 7;    // 0..7
    const unsigned FULL = 0xffffffffu;

    // ---- stage x[s] (2048 floats) coalesced ----
    {
        const float4* xg = reinterpret_cast<const float4*>(x + (size_t)s * B_DIM * E_DIM);
        float4* xd = reinterpret_cast<float4*>(xs);
        xd[t]       = xg[t];
        xd[t + 256] = xg[t + 256];
    }
    __syncthreads();

    const float4* xs4 = reinterpret_cast<const float4*>(xs);

    // ================= phase 1: k = x@Wk^T + bk, v = x@Wv^T + bv =================
    // thread: partial sums over j in {32i+4jo..+3, i=0..3} for e=4eg+r, all b.
    #pragma unroll
    for (int m = 0; m < 2; m++) {
        const float4* W4 = reinterpret_cast<const float4*>(m ? Wv : Wk);
        const float*  bias = m ? bv : bk;
        float* dst = m ? vs : ks;

        // W chunk in regs: w[r][i] = W[4eg+r][32i+4jo .. +3]
        // per warp-LDG: 8 jo lanes = 128B contiguous line, 4 eg rows -> 4 full lines
        float4 w[4][4];
        #pragma unroll
        for (int r = 0; r < 4; r++)
            #pragma unroll
            for (int i = 0; i < 4; i++)
                w[r][i] = W4[(4 * eg + r) * 32 + 8 * i + jo];

        #pragma unroll
        for (int bh = 0; bh < 2; bh++) {
            float acc[4][8];
            #pragma unroll
            for (int r = 0; r < 4; r++)
                #pragma unroll
                for (int b8 = 0; b8 < 8; b8++) acc[r][b8] = 0.0f;

            #pragma unroll
            for (int b8 = 0; b8 < 8; b8++) {
                const int b = bh * 8 + b8;
                float4 xv[4];
                #pragma unroll
                for (int i = 0; i < 4; i++) xv[i] = xs4[b * 32 + 8 * i + jo];
                #pragma unroll
                for (int r = 0; r < 4; r++) {
                    float a = acc[r][b8];
                    #pragma unroll
                    for (int i = 0; i < 4; i++) {
                        a = fmaf(w[r][i].x, xv[i].x, a);
                        a = fmaf(w[r][i].y, xv[i].y, a);
                        a = fmaf(w[r][i].z, xv[i].z, a);
                        a = fmaf(w[r][i].w, xv[i].w, a);
                    }
                    acc[r][b8] = a;
                }
            }

            // routed reduction over the 8 jo-lanes (xor 1,2,4).
            // final: lane jo holds sums for (r = jo&3, b8 = (jo>>2)*4 + q)
            const bool p0 = (jo & 1) != 0;
            const bool p1 = (jo & 2) != 0;
            const bool p2 = (jo & 4) != 0;

            float s16[2][8];
            #pragma unroll
            for (int rr = 0; rr < 2; rr++)
                #pragma unroll
                for (int b8 = 0; b8 < 8; b8++) {
                    const float keep = p0 ? acc[2 * rr + 1][b8] : acc[2 * rr][b8];
                    const float give = p0 ? acc[2 * rr][b8]     : acc[2 * rr + 1][b8];
                    s16[rr][b8] = keep + __shfl_xor_sync(FULL, give, 1);
                }
            float s8v[8];
            #pragma unroll
            for (int b8 = 0; b8 < 8; b8++) {
                const float keep = p1 ? s16[1][b8] : s16[0][b8];
                const float give = p1 ? s16[0][b8] : s16[1][b8];
                s8v[b8] = keep + __shfl_xor_sync(FULL, give, 2);
            }
            float s4v[4];
            #pragma unroll
            for (int q = 0; q < 4; q++) {
                const float keep = p2 ? s8v[4 + q] : s8v[q];
                const float give = p2 ? s8v[q]     : s8v[4 + q];
                s4v[q] = keep + __shfl_xor_sync(FULL, give, 4);
            }

            const int r  = jo & 3;
            const int bq = (jo >> 2) * 4;
            const float bb = __ldg(bias + 4 * eg + r);
            #pragma unroll
            for (int q = 0; q < 4; q++)
                dst[(bh * 8 + bq + q) * E_DIM + 4 * eg + r] = s4v[q] + bb;
        }
    }
    __syncthreads();

    const float4* ks4 = reinterpret_cast<const float4*>(ks);
    const float4* vs4 = reinterpret_cast<const float4*>(vs);

    // ================= phase 2: sc[r][c] = sum_b k[b][4eg+r] * v[b][F(c)] ============
    // F(4i+q) = 32i + 4jo + q
    float sc[4][16];
    #pragma unroll
    for (int r = 0; r < 4; r++)
        #pragma unroll
        for (int c = 0; c < 16; c++) sc[r][c] = 0.0f;

    #pragma unroll 2
    for (int b = 0; b < B_DIM; b++) {
        const float4 kk = ks4[b * 32 + eg];
        float4 vv[4];
        #pragma unroll
        for (int i = 0; i < 4; i++) vv[i] = vs4[b * 32 + 8 * i + jo];
        const float kr[4] = { kk.x, kk.y, kk.z, kk.w };
        #pragma unroll
        for (int r = 0; r < 4; r++)
            #pragma unroll
            for (int i = 0; i < 4; i++) {
                sc[r][4 * i + 0] = fmaf(kr[r], vv[i].x, sc[r][4 * i + 0]);
                sc[r][4 * i + 1] = fmaf(kr[r], vv[i].y, sc[r][4 * i + 1]);
                sc[r][4 * i + 2] = fmaf(kr[r], vv[i].z, sc[r][4 * i + 2]);
                sc[r][4 * i + 3] = fmaf(kr[r], vv[i].w, sc[r][4 * i + 3]);
            }
    }

    // ================= softmax over f (row spans the 8 jo-lanes) =================
    const float scale = 0.01104854345603993f; // 1/sqrt(8192)
    float inv[4];
    #pragma unroll
    for (int r = 0; r < 4; r++) {
        float mx = sc[r][0];
        #pragma unroll
        for (int c = 1; c < 16; c++) mx = fmaxf(mx, sc[r][c]);
        mx = fmaxf(mx, __shfl_xor_sync(FULL, mx, 1));
        mx = fmaxf(mx, __shfl_xor_sync(FULL, mx, 2));
        mx = fmaxf(mx, __shfl_xor_sync(FULL, mx, 4));

        float ssum = 0.0f;
        #pragma unroll
        for (int c = 0; c < 16; c++) {
            sc[r][c] = __expf((sc[r][c] - mx) * scale);
            ssum += sc[r][c];
        }
        ssum += __shfl_xor_sync(FULL, ssum, 1);
        ssum += __shfl_xor_sync(FULL, ssum, 2);
        ssum += __shfl_xor_sync(FULL, ssum, 4);
        inv[r] = 1.0f / ssum;
    }

    // ================= phase 3: out[b][4eg+r] = inv[r] * sum_f p[r][f] x[b][f] =======
    float* outp = out + (size_t)s * B_DIM * E_DIM;
    const bool p0 = (jo & 1) != 0;
    const bool p1 = (jo & 2) != 0;
    const bool p2 = (jo & 4) != 0;

    #pragma unroll
    for (int bc = 0; bc < 2; bc++) {
        float o[8][4];
        #pragma unroll
        for (int b8 = 0; b8 < 8; b8++)
            #pragma unroll
            for (int r = 0; r < 4; r++) o[b8][r] = 0.0f;

        #pragma unroll
        for (int b8 = 0; b8 < 8; b8++) {
            const int b = bc * 8 + b8;
            float4 xv[4];
            #pragma unroll
            for (int i = 0; i < 4; i++) xv[i] = xs4[b * 32 + 8 * i + jo];
            #pragma unroll
            for (int r = 0; r < 4; r++) {
                float a = o[b8][r];
                #pragma unroll
                for (int i = 0; i < 4; i++) {
                    a = fmaf(sc[r][4 * i + 0], xv[i].x, a);
                    a = fmaf(sc[r][4 * i + 1], xv[i].y, a);
                    a = fmaf(sc[r][4 * i + 2], xv[i].z, a);
                    a = fmaf(sc[r][4 * i + 3], xv[i].w, a);
                }
                o[b8][r] = a;
            }
        }

        // routed reduction: lane jo ends with b8 = jo (all 4 r)
        float u16[4][4];  // [b-pair][r]
        #pragma unroll
        for (int bp = 0; bp < 4; bp++)
            #pragma unroll
            for (int r = 0; r < 4; r++) {
                const float keep = p0 ? o[2 * bp + 1][r] : o[2 * bp][r];
                const float give = p0 ? o[2 * bp][r]     : o[2 * bp + 1][r];
                u16[bp][r] = keep + __shfl_xor_sync(FULL, give, 1);
            }
        float u8[2][4];
        #pragma unroll
        for (int bp = 0; bp < 2; bp++)
            #pragma unroll
            for (int r = 0; r < 4; r++) {
                const float keep = p1 ? u16[2 * bp + 1][r] : u16[2 * bp][r];
                const float give = p1 ? u16[2 * bp][r]     : u16[2 * bp + 1][r];
                u8[bp][r] = keep + __shfl_xor_sync(FULL, give, 2);
            }
        float res[4];
        #pragma unroll
        for (int r = 0; r < 4; r++) {
            const float keep = p2 ? u8[1][r] : u8[0][r];
            const float give = p2 ? u8[0][r] : u8[1][r];
            res[r] = keep + __shfl_xor_sync(FULL, give, 4);
        }

        const int b = bc * 8 + jo;
        float4 w4;
        w4.x = res[0] * inv[0];
        w4.y = res[1] * inv[1];
        w4.z = res[2] * inv[2];
        w4.w = res[3] * inv[3];
        *reinterpret_cast<float4*>(&outp[b * E_DIM + 4 * eg]) = w4;
    }
}

extern "C" void kernel_launch(void* const* d_in, const int* in_sizes, int n_in,
                              void* d_out, int out_size) {
    const float* x  = (const float*)d_in[0];
    const float* Wk = (const float*)d_in[1];
    const float* bk = (const float*)d_in[2];
    const float* Wv = (const float*)d_in[3];
    const float* bv = (const float*)d_in[4];
    float* out = (float*)d_out;
    nsa_kernel<<<S_TOTAL, 256>>>(x, Wk, bk, Wv, bv, out);
}